// round 14
// baseline (speedup 1.0000x reference)
#include <cuda_runtime.h>
#include <cuda_fp16.h>
#include <cstdint>
#include <mma.h>

using namespace nvcuda;

#define DV    512
#define NB    32
#define NS    1024
#define NBS   (NB*NS)      // 32768
#define NN    2048
#define KCONV 1536         // 3*512

// ---------------- scratch (static device globals; no allocs) ----------------
__device__ float g_Xs[NN*DV];     // Xs (GCN), later reused as fp32 G
__device__ float g_inv[NN];

__device__ half g_Ash[NN*NN];                       // A_sub hi (A-side only)
__device__ half g_XsTh[DV*NN],  g_XsTl[DV*NN];      // B-side: hi/lo
__device__ half g_AXh[NN*DV];                       // A-side only
__device__ half g_Hch[NN*DV];                       // A-side of G GEMM
__device__ half g_Gh[NN*DV];                        // G = Hc@hpw, logits B-side (hi only)
__device__ half g_gwh[DV*DV],   g_gwl[DV*DV];       // B-side
__device__ half g_hph[DV*DV],   g_hpl[DV*DV];       // hpw^T hi/lo (B-side of G)
__device__ half g_w1Th[DV*KCONV];                   // conv1 W^T hi (1-pass)
__device__ half g_w2Th[DV*KCONV];                   // conv2 W^T hi (1-pass)
__device__ half g_X0h[NBS*DV];                      // embedded input (fp16)
__device__ half g_Y1h[NBS*DV];                      // conv1 out (A-side only)
__device__ half g_Y2h[NBS*DV];                      // conv2+residual, then LN in place

// ---------------- helpers ----------------
__device__ __forceinline__ uint32_t smem_u32(const void* p) {
    uint32_t a;
    asm("{ .reg .u64 t; cvta.to.shared.u64 t, %1; cvt.u32.u64 %0, t; }" : "=r"(a) : "l"(p));
    return a;
}
__device__ __forceinline__ void cpa16(uint32_t d, const void* s, int sz) {
    asm volatile("cp.async.cg.shared.global [%0], [%1], 16, %2;" :: "r"(d), "l"(s), "r"(sz) : "memory");
}
__device__ __forceinline__ void split1(float v, half& h, half& l) {
    h = __float2half_rn(v);
    l = __float2half_rn(v - __half2float(h));
}

// ---------------- small kernels ----------------
__global__ void k_deg(const float* __restrict__ A, float* __restrict__ invs) {
    int i = blockIdx.x, tid = threadIdx.x;
    float s = 0.f;
    const float* row = A + (size_t)i * NN;
    for (int j = tid; j < NN; j += 256) s += row[j];
    __shared__ float sh[8];
    #pragma unroll
    for (int o = 16; o > 0; o >>= 1) s += __shfl_down_sync(0xffffffffu, s, o);
    if ((tid & 31) == 0) sh[tid >> 5] = s;
    __syncthreads();
    if (tid == 0) {
        float t = 0.f;
        #pragma unroll
        for (int w = 0; w < 8; w++) t += sh[w];
        t += 1.0f;
        t = fmaxf(t, 1e-6f);
        invs[i] = rsqrtf(t);
    }
}

__global__ void k_gather_xs(const int* __restrict__ sub_nodes, const float* __restrict__ embed,
                            const float* __restrict__ invs, float* __restrict__ Xs) {
    int j = blockIdx.x;
    int idx = sub_nodes[j];
    float sc = invs[j];
    const float4* src = (const float4*)(embed + (size_t)idx * DV);
    float4* dst = (float4*)(Xs + (size_t)j * DV);
    for (int t = threadIdx.x; t < DV / 4; t += blockDim.x) {
        float4 v = src[t];
        v.x *= sc; v.y *= sc; v.z *= sc; v.w *= sc;
        dst[t] = v;
    }
}

__global__ void k_split(const float4* __restrict__ src, half* __restrict__ h,
                        half* __restrict__ l, int n4) {
    int i = blockIdx.x * 256 + threadIdx.x;
    if (i >= n4) return;
    float4 v = src[i];
    half h0, h1, h2, h3, l0, l1, l2, l3;
    split1(v.x, h0, l0); split1(v.y, h1, l1); split1(v.z, h2, l2); split1(v.w, h3, l3);
    __half2* ph = (__half2*)h;
    __half2* pl = (__half2*)l;
    ph[2*i]   = __halves2half2(h0, h1);
    ph[2*i+1] = __halves2half2(h2, h3);
    pl[2*i]   = __halves2half2(l0, l1);
    pl[2*i+1] = __halves2half2(l2, l3);
}

__global__ void k_cvt_hi(const float4* __restrict__ src, half* __restrict__ h, int n4) {
    int i = blockIdx.x * 256 + threadIdx.x;
    if (i >= n4) return;
    float4 v = src[i];
    __half2* ph = (__half2*)h;
    ph[2*i]   = __halves2half2(__float2half_rn(v.x), __float2half_rn(v.y));
    ph[2*i+1] = __halves2half2(__float2half_rn(v.z), __float2half_rn(v.w));
}

// transpose + split: in[R,C] f32 -> out hi/lo [C,R] fp16 (ol may be null -> hi only)
__global__ void k_transpose_split(const float* __restrict__ in, half* __restrict__ oh,
                                  half* __restrict__ ol, int R, int C) {
    __shared__ float t[32][33];
    int c0 = blockIdx.x * 32, r0 = blockIdx.y * 32;
    #pragma unroll
    for (int j = 0; j < 32; j += 8)
        t[threadIdx.y + j][threadIdx.x] = in[(size_t)(r0 + threadIdx.y + j) * C + c0 + threadIdx.x];
    __syncthreads();
    #pragma unroll
    for (int j = 0; j < 32; j += 8) {
        float v = t[threadIdx.x][threadIdx.y + j];
        half h, l; split1(v, h, l);
        size_t o = (size_t)(c0 + threadIdx.y + j) * R + r0 + threadIdx.x;
        oh[o] = h;
        if (ol) ol[o] = l;
    }
}

// embed gather -> fp16 only
__global__ void k_embed_gather(const int* __restrict__ x_in, const int* __restrict__ mask,
                               const float* __restrict__ embed, half* __restrict__ X0h) {
    int r = blockIdx.x;
    int idx = x_in[r];
    float m = (mask[r] != 0) ? 1.f : 0.f;
    const float4* src = (const float4*)(embed + (size_t)idx * DV);
    for (int t = threadIdx.x; t < DV / 4; t += blockDim.x) {
        float4 v = src[t];
        v.x *= m; v.y *= m; v.z *= m; v.w *= m;
        size_t o = ((size_t)r * DV) / 2 + 2 * t;
        ((__half2*)X0h)[o]   = __halves2half2(__float2half_rn(v.x), __float2half_rn(v.y));
        ((__half2*)X0h)[o+1] = __halves2half2(__float2half_rn(v.z), __float2half_rn(v.w));
    }
}

// in-place layernorm + mask on fp16 rows (residual already folded in by conv2 epilogue)
__global__ void k_ln(half* __restrict__ y2h, const int* __restrict__ mask,
                     const float* __restrict__ g, const float* __restrict__ b) {
    int r = blockIdx.x, tid = threadIdx.x;
    size_t base = (size_t)r * DV;
    float v0 = __half2float(y2h[base + tid]);
    float v1 = __half2float(y2h[base + tid + 256]);
    float s = v0 + v1, s2 = v0 * v0 + v1 * v1;
    __shared__ float sh1[8], sh2[8];
    __shared__ float s_mu, s_iv;
    #pragma unroll
    for (int o = 16; o > 0; o >>= 1) {
        s  += __shfl_down_sync(0xffffffffu, s,  o);
        s2 += __shfl_down_sync(0xffffffffu, s2, o);
    }
    if ((tid & 31) == 0) { sh1[tid >> 5] = s; sh2[tid >> 5] = s2; }
    __syncthreads();
    if (tid == 0) {
        float t1 = 0.f, t2 = 0.f;
        #pragma unroll
        for (int w = 0; w < 8; w++) { t1 += sh1[w]; t2 += sh2[w]; }
        float mu = t1 * (1.0f / DV);
        float var = t2 * (1.0f / DV) - mu * mu;
        s_mu = mu; s_iv = rsqrtf(var + 1e-5f);
    }
    __syncthreads();
    float mu = s_mu, iv = s_iv;
    float m = (mask[r] != 0) ? 1.f : 0.f;
    float o0 = ((v0 - mu) * iv * g[tid]       + b[tid])       * m;
    float o1 = ((v1 - mu) * iv * g[tid + 256] + b[tid + 256]) * m;
    y2h[base + tid]       = __float2half_rn(o0);
    y2h[base + tid + 256] = __float2half_rn(o1);
}

// ---------------- fp16 GEMM, tile 128x128, BK=64, 256 thr, 2-stage, 2 CTA/SM ----
// C[m,n] = sum_k A[m,k]*Bt[n,k];  A: fp16 hi only.  BLO=1: B hi/lo 2-pass; BLO=0: hi only.
// EPI: 0 none(direct store), 1 bias, 2 bias+relu, 3 axs, 4 bias+fp16 residual(from Res)
// stage: A@0 (128 rows x 72 halves = 18432B), Bh@18432, Bl@36864; stage = 55296 B
#define STG    55296
#define SMEMSZ (2*STG)   // 110592; also covers 128x132 f32 epilogue buf (67584)

template <int MODE, int EPI, int OUT, int BLO>
__global__ void __launch_bounds__(256, 2)
mma_gemm(const half* __restrict__ Ah,
         const half* __restrict__ Bh, const half* __restrict__ Bl,
         const float* __restrict__ aux, const float* __restrict__ invs,
         float* __restrict__ Cf, half* __restrict__ Chi, const half* __restrict__ Res,
         int Ncols, int Kd, int lda) {
    extern __shared__ __align__(128) char smem[];
    uint32_t sb = smem_u32(smem);
    const int tid = threadIdx.x;
    const int bm = blockIdx.y << 7, bn = blockIdx.x << 7;
    const int w = tid >> 5;
    const int rm = (w >> 1) << 5;   // warp row base (0,32,64,96)
    const int cn = (w & 1) << 6;    // warp col base (0,64)

    wmma::fragment<wmma::accumulator, 16, 16, 16, float> acc[2][4];
    #pragma unroll
    for (int mt = 0; mt < 2; mt++)
        #pragma unroll
        for (int nt = 0; nt < 4; nt++) wmma::fill_fragment(acc[mt][nt], 0.f);

    const int nch = Kd >> 6;

    auto issue = [&](int ch) {
        int k0 = ch << 6;
        uint32_t st = sb + (uint32_t)(ch & 1) * STG;
        #pragma unroll
        for (int t = 0; t < 12; t++) {
            int c = tid + (t << 8);          // 0..3071
            int row = (c & 1023) >> 3;       // 0..127
            int seg = c & 7;                 // 16B segment within 64-wide K chunk
            uint32_t doff = (uint32_t)row * 144u + (uint32_t)(seg << 4);
            if (c < 1024) {
                if (MODE == 0) {
                    size_t so = (size_t)(bm + row) * lda + k0 + (seg << 3);
                    cpa16(st + doff, Ah + so, 16);
                } else {
                    int kk = k0 >> 9;        // tap, constant per 64-chunk
                    int icol = (k0 & 511) + (seg << 3);
                    int rg = bm + row;
                    int valid = ((rg & (NS - 1)) + kk) >= 2;
                    size_t so = (size_t)(valid ? rg + kk - 2 : rg) * 512 + icol;
                    cpa16(st + doff, Ah + so, valid ? 16 : 0);
                }
            } else if (c < 2048) {
                size_t so = (size_t)(bn + row) * Kd + k0 + (seg << 3);
                cpa16(st + 18432 + doff, Bh + so, 16);
            } else if (BLO) {
                size_t so = (size_t)(bn + row) * Kd + k0 + (seg << 3);
                cpa16(st + 36864 + doff, Bl + so, 16);
            }
        }
        asm volatile("cp.async.commit_group;" ::: "memory");
    };

    issue(0);

    for (int ch = 0; ch < nch; ch++) {
        __syncthreads();
        if (ch + 1 < nch) {
            issue(ch + 1);
            asm volatile("cp.async.wait_group 1;" ::: "memory");
        } else {
            asm volatile("cp.async.wait_group 0;" ::: "memory");
        }
        __syncthreads();

        const half* pA  = (const half*)(smem + (ch & 1) * STG);
        const half* pBh = pA + 9216;
        const half* pBl = pA + 18432;
        #pragma unroll
        for (int ks = 0; ks < 64; ks += 16) {
            wmma::fragment<wmma::matrix_a, 16, 16, 16, half, wmma::row_major> fah[2];
            #pragma unroll
            for (int mt = 0; mt < 2; mt++)
                wmma::load_matrix_sync(fah[mt], pA + (rm + mt * 16) * 72 + ks, 72);
            #pragma unroll
            for (int nt = 0; nt < 4; nt++) {
                wmma::fragment<wmma::matrix_b, 16, 16, 16, half, wmma::col_major> fbh;
                wmma::load_matrix_sync(fbh, pBh + (cn + nt * 16) * 72 + ks, 72);
                #pragma unroll
                for (int mt = 0; mt < 2; mt++)
                    wmma::mma_sync(acc[mt][nt], fah[mt], fbh, acc[mt][nt]);
                if (BLO) {
                    wmma::fragment<wmma::matrix_b, 16, 16, 16, half, wmma::col_major> fbl;
                    wmma::load_matrix_sync(fbl, pBl + (cn + nt * 16) * 72 + ks, 72);
                    #pragma unroll
                    for (int mt = 0; mt < 2; mt++)
                        wmma::mma_sync(acc[mt][nt], fah[mt], fbl, acc[mt][nt]);
                }
            }
        }
    }

    if (EPI == 0 && OUT == 0) {
        // direct fragment store to gmem (logits, G)
        #pragma unroll
        for (int mt = 0; mt < 2; mt++)
            #pragma unroll
            for (int nt = 0; nt < 4; nt++)
                wmma::store_matrix_sync(
                    Cf + (size_t)(bm + rm + mt * 16) * Ncols + bn + cn + nt * 16,
                    acc[mt][nt], Ncols, wmma::mem_row_major);
        return;
    }

    // ---- epilogue via smem (128x132 fp32 = 67584 B, covered by SMEMSZ) ----
    __syncthreads();
    float* Cbuf = (float*)smem;
    #pragma unroll
    for (int mt = 0; mt < 2; mt++)
        #pragma unroll
        for (int nt = 0; nt < 4; nt++)
            wmma::store_matrix_sync(Cbuf + (rm + mt * 16) * 132 + cn + nt * 16,
                                    acc[mt][nt], 132, wmma::mem_row_major);
    __syncthreads();

    int row = tid >> 1;
    int cp = (tid & 1) << 6;
    int grow = bm + row;
    float ivv = (EPI == 3) ? invs[grow] : 0.f;
    #pragma unroll
    for (int j = 0; j < 64; j += 4) {
        int col = cp + j;
        size_t off = (size_t)grow * Ncols + bn + col;
        float v0 = Cbuf[row * 132 + col + 0];
        float v1 = Cbuf[row * 132 + col + 1];
        float v2 = Cbuf[row * 132 + col + 2];
        float v3 = Cbuf[row * 132 + col + 3];
        if (EPI == 1 || EPI == 2 || EPI == 4) {
            float4 bi = *(const float4*)(aux + bn + col);
            v0 += bi.x; v1 += bi.y; v2 += bi.z; v3 += bi.w;
            if (EPI == 2) {
                v0 = fmaxf(v0, 0.f); v1 = fmaxf(v1, 0.f);
                v2 = fmaxf(v2, 0.f); v3 = fmaxf(v3, 0.f);
            }
            if (EPI == 4) {
                __half2 r01 = ((const __half2*)(Res + off))[0];
                __half2 r23 = ((const __half2*)(Res + off))[1];
                v0 += __half2float(__low2half(r01));  v1 += __half2float(__high2half(r01));
                v2 += __half2float(__low2half(r23));  v3 += __half2float(__high2half(r23));
            }
        } else if (EPI == 3) {
            float4 xs = *(const float4*)(aux + (size_t)grow * 512 + bn + col);
            v0 = ivv * (v0 + xs.x); v1 = ivv * (v1 + xs.y);
            v2 = ivv * (v2 + xs.z); v3 = ivv * (v3 + xs.w);
        }
        if (OUT == 0) {
            *(float4*)(Cf + off) = make_float4(v0, v1, v2, v3);
        } else {
            __half2* ph = (__half2*)(Chi + off);
            ph[0] = __halves2half2(__float2half_rn(v0), __float2half_rn(v1));
            ph[1] = __halves2half2(__float2half_rn(v2), __float2half_rn(v3));
        }
    }
}

// ---------------- launch ----------------
extern "C" void kernel_launch(void* const* d_in, const int* in_sizes, int n_in,
                              void* d_out, int out_size) {
    const int*   x_in  = (const int*)d_in[0];
    const int*   mask  = (const int*)d_in[1];
    const int*   subn  = (const int*)d_in[2];
    const float* A_sub = (const float*)d_in[3];
    const float* embed = (const float*)d_in[4];
    const float* c1w   = (const float*)d_in[5];
    const float* c1b   = (const float*)d_in[6];
    const float* c2w   = (const float*)d_in[7];
    const float* c2b   = (const float*)d_in[8];
    const float* lng   = (const float*)d_in[9];
    const float* lnb   = (const float*)d_in[10];
    const float* gcnw  = (const float*)d_in[11];
    const float* gcnb  = (const float*)d_in[12];
    const float* hpw   = (const float*)d_in[13];
    float*       out   = (float*)d_out;

    float *Xs, *inv;
    half *Ash, *XsTh, *XsTl, *AXh, *Hch, *Gh, *gwh, *gwl, *hph, *hpl;
    half *w1Th, *w2Th, *X0h, *Y1h, *Y2h;
    cudaGetSymbolAddress((void**)&Xs,  g_Xs);
    cudaGetSymbolAddress((void**)&inv, g_inv);
    cudaGetSymbolAddress((void**)&Ash, g_Ash);
    cudaGetSymbolAddress((void**)&XsTh, g_XsTh); cudaGetSymbolAddress((void**)&XsTl, g_XsTl);
    cudaGetSymbolAddress((void**)&AXh, g_AXh);
    cudaGetSymbolAddress((void**)&Hch, g_Hch);
    cudaGetSymbolAddress((void**)&Gh,  g_Gh);
    cudaGetSymbolAddress((void**)&gwh, g_gwh);   cudaGetSymbolAddress((void**)&gwl, g_gwl);
    cudaGetSymbolAddress((void**)&hph, g_hph);   cudaGetSymbolAddress((void**)&hpl, g_hpl);
    cudaGetSymbolAddress((void**)&w1Th, g_w1Th);
    cudaGetSymbolAddress((void**)&w2Th, g_w2Th);
    cudaGetSymbolAddress((void**)&X0h, g_X0h);
    cudaGetSymbolAddress((void**)&Y1h, g_Y1h);
    cudaGetSymbolAddress((void**)&Y2h, g_Y2h);

    cudaFuncSetAttribute(mma_gemm<0,3,1,1>, cudaFuncAttributeMaxDynamicSharedMemorySize, SMEMSZ);
    cudaFuncSetAttribute(mma_gemm<0,2,1,1>, cudaFuncAttributeMaxDynamicSharedMemorySize, SMEMSZ);
    cudaFuncSetAttribute(mma_gemm<1,2,1,0>, cudaFuncAttributeMaxDynamicSharedMemorySize, SMEMSZ);
    cudaFuncSetAttribute(mma_gemm<1,4,1,0>, cudaFuncAttributeMaxDynamicSharedMemorySize, SMEMSZ);
    cudaFuncSetAttribute(mma_gemm<0,0,0,1>, cudaFuncAttributeMaxDynamicSharedMemorySize, SMEMSZ);
    cudaFuncSetAttribute(mma_gemm<0,0,0,0>, cudaFuncAttributeMaxDynamicSharedMemorySize, SMEMSZ);

    // fork/join resources, created once (outside capture on the first call)
    static cudaStream_t s_gcn = nullptr;
    static cudaEvent_t ev_fork = nullptr, ev_join = nullptr;
    if (!s_gcn) {
        cudaStreamCreateWithFlags(&s_gcn, cudaStreamNonBlocking);
        cudaEventCreateWithFlags(&ev_fork, cudaEventDisableTiming);
        cudaEventCreateWithFlags(&ev_join, cudaEventDisableTiming);
    }
    cudaStream_t sm = cudaStreamPerThread;

    dim3 t32(32, 8);

    // ---- fork ----
    cudaEventRecord(ev_fork, sm);
    cudaStreamWaitEvent(s_gcn, ev_fork, 0);

    // ---- GCN branch (side stream) ----
    k_deg<<<NN, 256, 0, s_gcn>>>(A_sub, inv);
    k_gather_xs<<<NN, 128, 0, s_gcn>>>(subn, embed, inv, Xs);
    k_transpose_split<<<dim3(DV/32, NN/32), t32, 0, s_gcn>>>(Xs, XsTh, XsTl, NN, DV);
    k_cvt_hi<<<NN*NN/4/256, 256, 0, s_gcn>>>((const float4*)A_sub, Ash, NN*NN/4);
    mma_gemm<0,3,1,1><<<dim3(DV/128, NN/128), 256, SMEMSZ, s_gcn>>>(
        Ash, XsTh, XsTl, Xs, inv, nullptr, AXh, nullptr, DV, NN, NN);
    k_split<<<DV*DV/4/256, 256, 0, s_gcn>>>((const float4*)gcnw, gwh, gwl, DV*DV/4);
    mma_gemm<0,2,1,1><<<dim3(DV/128, NN/128), 256, SMEMSZ, s_gcn>>>(
        AXh, gwh, gwl, gcnb, nullptr, nullptr, Hch, nullptr, DV, DV, DV);
    k_transpose_split<<<dim3(DV/32, DV/32), t32, 0, s_gcn>>>(hpw, hph, hpl, DV, DV);
    mma_gemm<0,0,0,1><<<dim3(DV/128, NN/128), 256, SMEMSZ, s_gcn>>>(
        Hch, hph, hpl, nullptr, nullptr, Xs, nullptr, nullptr, DV, DV, DV);
    k_cvt_hi<<<NN*DV/4/256, 256, 0, s_gcn>>>((const float4*)Xs, Gh, NN*DV/4);
    cudaEventRecord(ev_join, s_gcn);

    // ---- encoder branch (main stream) ----
    k_embed_gather<<<NBS, 128, 0, sm>>>(x_in, mask, embed, X0h);
    k_transpose_split<<<dim3(DV/32, KCONV/32), t32, 0, sm>>>(c1w, w1Th, nullptr, KCONV, DV);
    k_transpose_split<<<dim3(DV/32, KCONV/32), t32, 0, sm>>>(c2w, w2Th, nullptr, KCONV, DV);
    mma_gemm<1,2,1,0><<<dim3(DV/128, NBS/128), 256, SMEMSZ, sm>>>(
        X0h, w1Th, nullptr, c1b, nullptr, nullptr, Y1h, nullptr, DV, KCONV, 512);
    // conv2 + bias + fp16 residual (X0h) -> fp16 Y2h
    mma_gemm<1,4,1,0><<<dim3(DV/128, NBS/128), 256, SMEMSZ, sm>>>(
        Y1h, w2Th, nullptr, c2b, nullptr, nullptr, Y2h, X0h, DV, KCONV, 512);
    k_ln<<<NBS, 256, 0, sm>>>(Y2h, mask, lng, lnb);

    // ---- join, then logits = y @ G^T (1-pass, direct fragment store) ----
    cudaStreamWaitEvent(sm, ev_join, 0);
    mma_gemm<0,0,0,0><<<dim3(NN/128, NBS/128), 256, SMEMSZ, sm>>>(
        Y2h, Gh, nullptr, nullptr, nullptr, out, nullptr, nullptr, NN, DV, DV);
}

// round 15
// speedup vs baseline: 1.0693x; 1.0693x over previous
#include <cuda_runtime.h>
#include <cuda_fp16.h>
#include <cstdint>
#include <mma.h>

using namespace nvcuda;

#define DV    512
#define NB    32
#define NS    1024
#define NBS   (NB*NS)      // 32768
#define NN    2048
#define KCONV 1536         // 3*512

// ---------------- scratch (static device globals; no allocs) ----------------
__device__ float g_Y2[NBS*DV];
__device__ float g_Xs[NN*DV];     // Xs (GCN), later reused as fp32 G
__device__ float g_inv[NN];

__device__ half g_Ash[NN*NN];                       // A_sub hi (A-side only)
__device__ half g_XsTh[DV*NN],  g_XsTl[DV*NN];      // B-side: hi/lo
__device__ half g_AXh[NN*DV];                       // A-side only
__device__ half g_Hch[NN*DV];                       // A-side of G GEMM
__device__ half g_Gh[NN*DV];                        // G = Hc@hpw, logits B-side (hi only)
__device__ half g_gwh[DV*DV],   g_gwl[DV*DV];       // B-side
__device__ half g_hph[DV*DV],   g_hpl[DV*DV];       // hpw^T hi/lo (B-side of G)
__device__ half g_w1Th[DV*KCONV];                   // conv1 W^T hi (1-pass)
__device__ half g_w2Th[DV*KCONV];                   // conv2 W^T hi (1-pass)
__device__ half g_X0h[NBS*DV];                      // embedded input (fp16)
__device__ half g_Y1h[NBS*DV];                      // conv1 out (A-side only)
__device__ half g_Y2h[NBS*DV];                      // LN out (A-side of logits)

// ---------------- helpers ----------------
__device__ __forceinline__ uint32_t smem_u32(const void* p) {
    uint32_t a;
    asm("{ .reg .u64 t; cvta.to.shared.u64 t, %1; cvt.u32.u64 %0, t; }" : "=r"(a) : "l"(p));
    return a;
}
__device__ __forceinline__ void cpa16(uint32_t d, const void* s, int sz) {
    asm volatile("cp.async.cg.shared.global [%0], [%1], 16, %2;" :: "r"(d), "l"(s), "r"(sz) : "memory");
}
__device__ __forceinline__ void split1(float v, half& h, half& l) {
    h = __float2half_rn(v);
    l = __float2half_rn(v - __half2float(h));
}

// ---------------- small kernels ----------------
__global__ void k_deg(const float* __restrict__ A, float* __restrict__ invs) {
    int i = blockIdx.x, tid = threadIdx.x;
    float s = 0.f;
    const float* row = A + (size_t)i * NN;
    for (int j = tid; j < NN; j += 256) s += row[j];
    __shared__ float sh[8];
    #pragma unroll
    for (int o = 16; o > 0; o >>= 1) s += __shfl_down_sync(0xffffffffu, s, o);
    if ((tid & 31) == 0) sh[tid >> 5] = s;
    __syncthreads();
    if (tid == 0) {
        float t = 0.f;
        #pragma unroll
        for (int w = 0; w < 8; w++) t += sh[w];
        t += 1.0f;
        t = fmaxf(t, 1e-6f);
        invs[i] = rsqrtf(t);
    }
}

__global__ void k_gather_xs(const int* __restrict__ sub_nodes, const float* __restrict__ embed,
                            const float* __restrict__ invs, float* __restrict__ Xs) {
    int j = blockIdx.x;
    int idx = sub_nodes[j];
    float sc = invs[j];
    const float4* src = (const float4*)(embed + (size_t)idx * DV);
    float4* dst = (float4*)(Xs + (size_t)j * DV);
    for (int t = threadIdx.x; t < DV / 4; t += blockDim.x) {
        float4 v = src[t];
        v.x *= sc; v.y *= sc; v.z *= sc; v.w *= sc;
        dst[t] = v;
    }
}

__global__ void k_split(const float4* __restrict__ src, half* __restrict__ h,
                        half* __restrict__ l, int n4) {
    int i = blockIdx.x * 256 + threadIdx.x;
    if (i >= n4) return;
    float4 v = src[i];
    half h0, h1, h2, h3, l0, l1, l2, l3;
    split1(v.x, h0, l0); split1(v.y, h1, l1); split1(v.z, h2, l2); split1(v.w, h3, l3);
    __half2* ph = (__half2*)h;
    __half2* pl = (__half2*)l;
    ph[2*i]   = __halves2half2(h0, h1);
    ph[2*i+1] = __halves2half2(h2, h3);
    pl[2*i]   = __halves2half2(l0, l1);
    pl[2*i+1] = __halves2half2(l2, l3);
}

__global__ void k_cvt_hi(const float4* __restrict__ src, half* __restrict__ h, int n4) {
    int i = blockIdx.x * 256 + threadIdx.x;
    if (i >= n4) return;
    float4 v = src[i];
    __half2* ph = (__half2*)h;
    ph[2*i]   = __halves2half2(__float2half_rn(v.x), __float2half_rn(v.y));
    ph[2*i+1] = __halves2half2(__float2half_rn(v.z), __float2half_rn(v.w));
}

// transpose + split: in[R,C] f32 -> out hi/lo [C,R] fp16 (ol may be null -> hi only)
__global__ void k_transpose_split(const float* __restrict__ in, half* __restrict__ oh,
                                  half* __restrict__ ol, int R, int C) {
    __shared__ float t[32][33];
    int c0 = blockIdx.x * 32, r0 = blockIdx.y * 32;
    #pragma unroll
    for (int j = 0; j < 32; j += 8)
        t[threadIdx.y + j][threadIdx.x] = in[(size_t)(r0 + threadIdx.y + j) * C + c0 + threadIdx.x];
    __syncthreads();
    #pragma unroll
    for (int j = 0; j < 32; j += 8) {
        float v = t[threadIdx.x][threadIdx.y + j];
        half h, l; split1(v, h, l);
        size_t o = (size_t)(c0 + threadIdx.y + j) * R + r0 + threadIdx.x;
        oh[o] = h;
        if (ol) ol[o] = l;
    }
}

// embed gather -> fp16 only
__global__ void k_embed_gather(const int* __restrict__ x_in, const int* __restrict__ mask,
                               const float* __restrict__ embed, half* __restrict__ X0h) {
    int r = blockIdx.x;
    int idx = x_in[r];
    float m = (mask[r] != 0) ? 1.f : 0.f;
    const float4* src = (const float4*)(embed + (size_t)idx * DV);
    for (int t = threadIdx.x; t < DV / 4; t += blockDim.x) {
        float4 v = src[t];
        v.x *= m; v.y *= m; v.z *= m; v.w *= m;
        size_t o = ((size_t)r * DV) / 2 + 2 * t;
        ((__half2*)X0h)[o]   = __halves2half2(__float2half_rn(v.x), __float2half_rn(v.y));
        ((__half2*)X0h)[o+1] = __halves2half2(__float2half_rn(v.z), __float2half_rn(v.w));
    }
}

// residual (fp16 x0) + layernorm + mask -> fp16
__global__ void k_ln(const float* __restrict__ y2, const half* __restrict__ x0h,
                     const int* __restrict__ mask,
                     const float* __restrict__ g, const float* __restrict__ b,
                     half* __restrict__ oh) {
    int r = blockIdx.x, tid = threadIdx.x;
    size_t base = (size_t)r * DV;
    float v0 = y2[base + tid]       + __half2float(x0h[base + tid]);
    float v1 = y2[base + tid + 256] + __half2float(x0h[base + tid + 256]);
    float s = v0 + v1, s2 = v0 * v0 + v1 * v1;
    __shared__ float sh1[8], sh2[8];
    __shared__ float s_mu, s_iv;
    #pragma unroll
    for (int o = 16; o > 0; o >>= 1) {
        s  += __shfl_down_sync(0xffffffffu, s,  o);
        s2 += __shfl_down_sync(0xffffffffu, s2, o);
    }
    if ((tid & 31) == 0) { sh1[tid >> 5] = s; sh2[tid >> 5] = s2; }
    __syncthreads();
    if (tid == 0) {
        float t1 = 0.f, t2 = 0.f;
        #pragma unroll
        for (int w = 0; w < 8; w++) { t1 += sh1[w]; t2 += sh2[w]; }
        float mu = t1 * (1.0f / DV);
        float var = t2 * (1.0f / DV) - mu * mu;
        s_mu = mu; s_iv = rsqrtf(var + 1e-5f);
    }
    __syncthreads();
    float mu = s_mu, iv = s_iv;
    float m = (mask[r] != 0) ? 1.f : 0.f;
    float o0 = ((v0 - mu) * iv * g[tid]       + b[tid])       * m;
    float o1 = ((v1 - mu) * iv * g[tid + 256] + b[tid + 256]) * m;
    oh[base + tid]       = __float2half_rn(o0);
    oh[base + tid + 256] = __float2half_rn(o1);
}

// ---------------- fp16 GEMM, tile 128x128, BK=64, 256 thr, 2 CTA/SM ----
// C[m,n] = sum_k A[m,k]*Bt[n,k];  A: fp16 hi only.
// BLO=1: B hi/lo 2-pass, 2-stage pipeline (stage 55296 B).
// BLO=0: B hi only,      3-stage pipeline (stage 36864 B).
#define SMEMSZ 110592   // = 2*55296 = 3*36864; also covers 128x132 f32 epilogue (67584)

template <int MODE, int EPI, int OUT, int BLO>
__global__ void __launch_bounds__(256, 2)
mma_gemm(const half* __restrict__ Ah,
         const half* __restrict__ Bh, const half* __restrict__ Bl,
         const float* __restrict__ aux, const float* __restrict__ invs,
         float* __restrict__ Cf, half* __restrict__ Chi, half* __restrict__ Clo,
         int Ncols, int Kd, int lda) {
    constexpr int NSTG = BLO ? 2 : 3;
    constexpr uint32_t STGSZ = BLO ? 55296u : 36864u;
    extern __shared__ __align__(128) char smem[];
    uint32_t sb = smem_u32(smem);
    const int tid = threadIdx.x;
    const int bm = blockIdx.y << 7, bn = blockIdx.x << 7;
    const int w = tid >> 5;
    const int rm = (w >> 1) << 5;   // warp row base (0,32,64,96)
    const int cn = (w & 1) << 6;    // warp col base (0,64)

    wmma::fragment<wmma::accumulator, 16, 16, 16, float> acc[2][4];
    #pragma unroll
    for (int mt = 0; mt < 2; mt++)
        #pragma unroll
        for (int nt = 0; nt < 4; nt++) wmma::fill_fragment(acc[mt][nt], 0.f);

    const int nch = Kd >> 6;

    auto issue = [&](int ch) {
        int k0 = ch << 6;
        uint32_t st = sb + (uint32_t)(ch % NSTG) * STGSZ;
        #pragma unroll
        for (int t = 0; t < 12; t++) {
            int c = tid + (t << 8);          // 0..3071
            if (!BLO && c >= 2048) break;    // no Bl region in 3-stage mode
            int row = (c & 1023) >> 3;       // 0..127
            int seg = c & 7;                 // 16B segment within 64-wide K chunk
            uint32_t doff = (uint32_t)row * 144u + (uint32_t)(seg << 4);
            if (c < 1024) {
                if (MODE == 0) {
                    size_t so = (size_t)(bm + row) * lda + k0 + (seg << 3);
                    cpa16(st + doff, Ah + so, 16);
                } else {
                    int kk = k0 >> 9;        // tap, constant per 64-chunk
                    int icol = (k0 & 511) + (seg << 3);
                    int rg = bm + row;
                    int valid = ((rg & (NS - 1)) + kk) >= 2;
                    size_t so = (size_t)(valid ? rg + kk - 2 : rg) * 512 + icol;
                    cpa16(st + doff, Ah + so, valid ? 16 : 0);
                }
            } else if (c < 2048) {
                size_t so = (size_t)(bn + row) * Kd + k0 + (seg << 3);
                cpa16(st + 18432 + doff, Bh + so, 16);
            } else {
                size_t so = (size_t)(bn + row) * Kd + k0 + (seg << 3);
                cpa16(st + 36864 + doff, Bl + so, 16);
            }
        }
        asm volatile("cp.async.commit_group;" ::: "memory");
    };

    issue(0);
    if (NSTG == 3 && nch > 1) issue(1);

    for (int ch = 0; ch < nch; ch++) {
        __syncthreads();
        if (NSTG == 3) {
            if (ch + 2 < nch) {
                issue(ch + 2);
                asm volatile("cp.async.wait_group 2;" ::: "memory");
            } else if (ch + 1 < nch) {
                asm volatile("cp.async.wait_group 1;" ::: "memory");
            } else {
                asm volatile("cp.async.wait_group 0;" ::: "memory");
            }
        } else {
            if (ch + 1 < nch) {
                issue(ch + 1);
                asm volatile("cp.async.wait_group 1;" ::: "memory");
            } else {
                asm volatile("cp.async.wait_group 0;" ::: "memory");
            }
        }
        __syncthreads();

        const half* pA  = (const half*)(smem + (ch % NSTG) * STGSZ);
        const half* pBh = pA + 9216;
        const half* pBl = pA + 18432;
        #pragma unroll
        for (int ks = 0; ks < 64; ks += 16) {
            wmma::fragment<wmma::matrix_a, 16, 16, 16, half, wmma::row_major> fah[2];
            #pragma unroll
            for (int mt = 0; mt < 2; mt++)
                wmma::load_matrix_sync(fah[mt], pA + (rm + mt * 16) * 72 + ks, 72);
            #pragma unroll
            for (int nt = 0; nt < 4; nt++) {
                wmma::fragment<wmma::matrix_b, 16, 16, 16, half, wmma::col_major> fbh;
                wmma::load_matrix_sync(fbh, pBh + (cn + nt * 16) * 72 + ks, 72);
                #pragma unroll
                for (int mt = 0; mt < 2; mt++)
                    wmma::mma_sync(acc[mt][nt], fah[mt], fbh, acc[mt][nt]);
                if (BLO) {
                    wmma::fragment<wmma::matrix_b, 16, 16, 16, half, wmma::col_major> fbl;
                    wmma::load_matrix_sync(fbl, pBl + (cn + nt * 16) * 72 + ks, 72);
                    #pragma unroll
                    for (int mt = 0; mt < 2; mt++)
                        wmma::mma_sync(acc[mt][nt], fah[mt], fbl, acc[mt][nt]);
                }
            }
        }
    }

    if (EPI == 0 && OUT == 0) {
        // direct fragment store to gmem (logits, G)
        #pragma unroll
        for (int mt = 0; mt < 2; mt++)
            #pragma unroll
            for (int nt = 0; nt < 4; nt++)
                wmma::store_matrix_sync(
                    Cf + (size_t)(bm + rm + mt * 16) * Ncols + bn + cn + nt * 16,
                    acc[mt][nt], Ncols, wmma::mem_row_major);
        return;
    }

    // ---- epilogue via smem (128x132 fp32 = 67584 B, covered by SMEMSZ) ----
    __syncthreads();
    float* Cbuf = (float*)smem;
    #pragma unroll
    for (int mt = 0; mt < 2; mt++)
        #pragma unroll
        for (int nt = 0; nt < 4; nt++)
            wmma::store_matrix_sync(Cbuf + (rm + mt * 16) * 132 + cn + nt * 16,
                                    acc[mt][nt], 132, wmma::mem_row_major);
    __syncthreads();

    int row = tid >> 1;
    int cp = (tid & 1) << 6;
    int grow = bm + row;
    float ivv = (EPI == 3) ? invs[grow] : 0.f;
    #pragma unroll
    for (int j = 0; j < 64; j += 4) {
        int col = cp + j;
        float v0 = Cbuf[row * 132 + col + 0];
        float v1 = Cbuf[row * 132 + col + 1];
        float v2 = Cbuf[row * 132 + col + 2];
        float v3 = Cbuf[row * 132 + col + 3];
        if (EPI == 1 || EPI == 2) {
            float4 bi = *(const float4*)(aux + bn + col);
            v0 += bi.x; v1 += bi.y; v2 += bi.z; v3 += bi.w;
            if (EPI == 2) {
                v0 = fmaxf(v0, 0.f); v1 = fmaxf(v1, 0.f);
                v2 = fmaxf(v2, 0.f); v3 = fmaxf(v3, 0.f);
            }
        } else if (EPI == 3) {
            float4 xs = *(const float4*)(aux + (size_t)grow * 512 + bn + col);
            v0 = ivv * (v0 + xs.x); v1 = ivv * (v1 + xs.y);
            v2 = ivv * (v2 + xs.z); v3 = ivv * (v3 + xs.w);
        }
        size_t off = (size_t)grow * Ncols + bn + col;
        if (OUT == 0) {
            *(float4*)(Cf + off) = make_float4(v0, v1, v2, v3);
        } else {
            __half2* ph = (__half2*)(Chi + off);
            ph[0] = __halves2half2(__float2half_rn(v0), __float2half_rn(v1));
            ph[1] = __halves2half2(__float2half_rn(v2), __float2half_rn(v3));
        }
    }
}

// ---------------- launch ----------------
extern "C" void kernel_launch(void* const* d_in, const int* in_sizes, int n_in,
                              void* d_out, int out_size) {
    const int*   x_in  = (const int*)d_in[0];
    const int*   mask  = (const int*)d_in[1];
    const int*   subn  = (const int*)d_in[2];
    const float* A_sub = (const float*)d_in[3];
    const float* embed = (const float*)d_in[4];
    const float* c1w   = (const float*)d_in[5];
    const float* c1b   = (const float*)d_in[6];
    const float* c2w   = (const float*)d_in[7];
    const float* c2b   = (const float*)d_in[8];
    const float* lng   = (const float*)d_in[9];
    const float* lnb   = (const float*)d_in[10];
    const float* gcnw  = (const float*)d_in[11];
    const float* gcnb  = (const float*)d_in[12];
    const float* hpw   = (const float*)d_in[13];
    float*       out   = (float*)d_out;

    float *Y2, *Xs, *inv;
    half *Ash, *XsTh, *XsTl, *AXh, *Hch, *Gh, *gwh, *gwl, *hph, *hpl;
    half *w1Th, *w2Th, *X0h, *Y1h, *Y2h;
    cudaGetSymbolAddress((void**)&Y2,  g_Y2);
    cudaGetSymbolAddress((void**)&Xs,  g_Xs);
    cudaGetSymbolAddress((void**)&inv, g_inv);
    cudaGetSymbolAddress((void**)&Ash, g_Ash);
    cudaGetSymbolAddress((void**)&XsTh, g_XsTh); cudaGetSymbolAddress((void**)&XsTl, g_XsTl);
    cudaGetSymbolAddress((void**)&AXh, g_AXh);
    cudaGetSymbolAddress((void**)&Hch, g_Hch);
    cudaGetSymbolAddress((void**)&Gh,  g_Gh);
    cudaGetSymbolAddress((void**)&gwh, g_gwh);   cudaGetSymbolAddress((void**)&gwl, g_gwl);
    cudaGetSymbolAddress((void**)&hph, g_hph);   cudaGetSymbolAddress((void**)&hpl, g_hpl);
    cudaGetSymbolAddress((void**)&w1Th, g_w1Th);
    cudaGetSymbolAddress((void**)&w2Th, g_w2Th);
    cudaGetSymbolAddress((void**)&X0h, g_X0h);
    cudaGetSymbolAddress((void**)&Y1h, g_Y1h);
    cudaGetSymbolAddress((void**)&Y2h, g_Y2h);

    cudaFuncSetAttribute(mma_gemm<0,3,1,1>, cudaFuncAttributeMaxDynamicSharedMemorySize, SMEMSZ);
    cudaFuncSetAttribute(mma_gemm<0,2,1,1>, cudaFuncAttributeMaxDynamicSharedMemorySize, SMEMSZ);
    cudaFuncSetAttribute(mma_gemm<1,2,1,0>, cudaFuncAttributeMaxDynamicSharedMemorySize, SMEMSZ);
    cudaFuncSetAttribute(mma_gemm<1,1,0,0>, cudaFuncAttributeMaxDynamicSharedMemorySize, SMEMSZ);
    cudaFuncSetAttribute(mma_gemm<0,0,0,1>, cudaFuncAttributeMaxDynamicSharedMemorySize, SMEMSZ);
    cudaFuncSetAttribute(mma_gemm<0,0,0,0>, cudaFuncAttributeMaxDynamicSharedMemorySize, SMEMSZ);

    // fork/join resources, created once (outside capture on the first call)
    static cudaStream_t s_gcn = nullptr;
    static cudaEvent_t ev_fork = nullptr, ev_join = nullptr;
    if (!s_gcn) {
        cudaStreamCreateWithFlags(&s_gcn, cudaStreamNonBlocking);
        cudaEventCreateWithFlags(&ev_fork, cudaEventDisableTiming);
        cudaEventCreateWithFlags(&ev_join, cudaEventDisableTiming);
    }
    cudaStream_t sm = cudaStreamPerThread;

    dim3 t32(32, 8);

    // ---- fork ----
    cudaEventRecord(ev_fork, sm);
    cudaStreamWaitEvent(s_gcn, ev_fork, 0);

    // ---- GCN branch (side stream) ----
    k_deg<<<NN, 256, 0, s_gcn>>>(A_sub, inv);
    k_gather_xs<<<NN, 128, 0, s_gcn>>>(subn, embed, inv, Xs);
    k_transpose_split<<<dim3(DV/32, NN/32), t32, 0, s_gcn>>>(Xs, XsTh, XsTl, NN, DV);
    k_cvt_hi<<<NN*NN/4/256, 256, 0, s_gcn>>>((const float4*)A_sub, Ash, NN*NN/4);
    mma_gemm<0,3,1,1><<<dim3(DV/128, NN/128), 256, SMEMSZ, s_gcn>>>(
        Ash, XsTh, XsTl, Xs, inv, nullptr, AXh, nullptr, DV, NN, NN);
    k_split<<<DV*DV/4/256, 256, 0, s_gcn>>>((const float4*)gcnw, gwh, gwl, DV*DV/4);
    mma_gemm<0,2,1,1><<<dim3(DV/128, NN/128), 256, SMEMSZ, s_gcn>>>(
        AXh, gwh, gwl, gcnb, nullptr, nullptr, Hch, nullptr, DV, DV, DV);
    k_transpose_split<<<dim3(DV/32, DV/32), t32, 0, s_gcn>>>(hpw, hph, hpl, DV, DV);
    mma_gemm<0,0,0,1><<<dim3(DV/128, NN/128), 256, SMEMSZ, s_gcn>>>(
        Hch, hph, hpl, nullptr, nullptr, Xs, nullptr, nullptr, DV, DV, DV);
    k_cvt_hi<<<NN*DV/4/256, 256, 0, s_gcn>>>((const float4*)Xs, Gh, NN*DV/4);
    cudaEventRecord(ev_join, s_gcn);

    // ---- encoder branch (main stream) ----
    k_embed_gather<<<NBS, 128, 0, sm>>>(x_in, mask, embed, X0h);
    k_transpose_split<<<dim3(DV/32, KCONV/32), t32, 0, sm>>>(c1w, w1Th, nullptr, KCONV, DV);
    k_transpose_split<<<dim3(DV/32, KCONV/32), t32, 0, sm>>>(c2w, w2Th, nullptr, KCONV, DV);
    mma_gemm<1,2,1,0><<<dim3(DV/128, NBS/128), 256, SMEMSZ, sm>>>(
        X0h, w1Th, nullptr, c1b, nullptr, nullptr, Y1h, nullptr, DV, KCONV, 512);
    mma_gemm<1,1,0,0><<<dim3(DV/128, NBS/128), 256, SMEMSZ, sm>>>(
        Y1h, w2Th, nullptr, c2b, nullptr, Y2, nullptr, nullptr, DV, KCONV, 512);
    k_ln<<<NBS, 256, 0, sm>>>(Y2, X0h, mask, lng, lnb, Y2h);

    // ---- join, then logits = y @ G^T (1-pass, direct fragment store) ----
    cudaStreamWaitEvent(sm, ev_join, 0);
    mma_gemm<0,0,0,0><<<dim3(NN/128, NBS/128), 256, SMEMSZ, sm>>>(
        Y2h, Gh, nullptr, nullptr, nullptr, out, nullptr, nullptr, NN, DV, DV);
}

// round 16
// speedup vs baseline: 1.0757x; 1.0060x over previous
#include <cuda_runtime.h>
#include <cuda_fp16.h>
#include <cstdint>
#include <mma.h>

using namespace nvcuda;

#define DV    512
#define NB    32
#define NS    1024
#define NBS   (NB*NS)      // 32768
#define NN    2048
#define KCONV 1536         // 3*512

// ---------------- scratch (static device globals; no allocs) ----------------
__device__ float g_Y2[NBS*DV];
__device__ float g_Xs[NN*DV];     // Xs (GCN), later reused as fp32 G
__device__ float g_inv[NN];

__device__ half g_Ash[NN*NN];                       // A_sub hi (A-side only)
__device__ half g_XsTh[DV*NN],  g_XsTl[DV*NN];      // B-side: hi/lo
__device__ half g_AXh[NN*DV];                       // A-side only
__device__ half g_Hch[NN*DV];                       // A-side of G GEMM
__device__ half g_Gh[NN*DV];                        // G = Hc@hpw, logits B-side (hi only)
__device__ half g_gwh[DV*DV],   g_gwl[DV*DV];       // B-side
__device__ half g_hph[DV*DV],   g_hpl[DV*DV];       // hpw^T hi/lo (B-side of G)
__device__ half g_w1Th[DV*KCONV];                   // conv1 W^T hi (1-pass)
__device__ half g_w2Th[DV*KCONV];                   // conv2 W^T hi (1-pass)
__device__ half g_X0h[NBS*DV];                      // embedded input (fp16)
__device__ half g_Y1h[NBS*DV];                      // conv1 out (A-side only)
__device__ half g_Y2h[NBS*DV];                      // LN out (A-side of logits)

// ---------------- helpers ----------------
__device__ __forceinline__ uint32_t smem_u32(const void* p) {
    uint32_t a;
    asm("{ .reg .u64 t; cvta.to.shared.u64 t, %1; cvt.u32.u64 %0, t; }" : "=r"(a) : "l"(p));
    return a;
}
__device__ __forceinline__ void cpa16(uint32_t d, const void* s, int sz) {
    asm volatile("cp.async.cg.shared.global [%0], [%1], 16, %2;" :: "r"(d), "l"(s), "r"(sz) : "memory");
}
__device__ __forceinline__ void split1(float v, half& h, half& l) {
    h = __float2half_rn(v);
    l = __float2half_rn(v - __half2float(h));
}

// ---------------- small kernels ----------------
__global__ void k_deg(const float* __restrict__ A, float* __restrict__ invs) {
    int i = blockIdx.x, tid = threadIdx.x;
    float s = 0.f;
    const float* row = A + (size_t)i * NN;
    for (int j = tid; j < NN; j += 256) s += row[j];
    __shared__ float sh[8];
    #pragma unroll
    for (int o = 16; o > 0; o >>= 1) s += __shfl_down_sync(0xffffffffu, s, o);
    if ((tid & 31) == 0) sh[tid >> 5] = s;
    __syncthreads();
    if (tid == 0) {
        float t = 0.f;
        #pragma unroll
        for (int w = 0; w < 8; w++) t += sh[w];
        t += 1.0f;
        t = fmaxf(t, 1e-6f);
        invs[i] = rsqrtf(t);
    }
}

__global__ void k_gather_xs(const int* __restrict__ sub_nodes, const float* __restrict__ embed,
                            const float* __restrict__ invs, float* __restrict__ Xs) {
    int j = blockIdx.x;
    int idx = sub_nodes[j];
    float sc = invs[j];
    const float4* src = (const float4*)(embed + (size_t)idx * DV);
    float4* dst = (float4*)(Xs + (size_t)j * DV);
    for (int t = threadIdx.x; t < DV / 4; t += blockDim.x) {
        float4 v = src[t];
        v.x *= sc; v.y *= sc; v.z *= sc; v.w *= sc;
        dst[t] = v;
    }
}

__global__ void k_split(const float4* __restrict__ src, half* __restrict__ h,
                        half* __restrict__ l, int n4) {
    int i = blockIdx.x * 256 + threadIdx.x;
    if (i >= n4) return;
    float4 v = src[i];
    half h0, h1, h2, h3, l0, l1, l2, l3;
    split1(v.x, h0, l0); split1(v.y, h1, l1); split1(v.z, h2, l2); split1(v.w, h3, l3);
    __half2* ph = (__half2*)h;
    __half2* pl = (__half2*)l;
    ph[2*i]   = __halves2half2(h0, h1);
    ph[2*i+1] = __halves2half2(h2, h3);
    pl[2*i]   = __halves2half2(l0, l1);
    pl[2*i+1] = __halves2half2(l2, l3);
}

__global__ void k_cvt_hi(const float4* __restrict__ src, half* __restrict__ h, int n4) {
    int i = blockIdx.x * 256 + threadIdx.x;
    if (i >= n4) return;
    float4 v = src[i];
    __half2* ph = (__half2*)h;
    ph[2*i]   = __halves2half2(__float2half_rn(v.x), __float2half_rn(v.y));
    ph[2*i+1] = __halves2half2(__float2half_rn(v.z), __float2half_rn(v.w));
}

// transpose + split: in[R,C] f32 -> out hi/lo [C,R] fp16 (ol may be null -> hi only)
__global__ void k_transpose_split(const float* __restrict__ in, half* __restrict__ oh,
                                  half* __restrict__ ol, int R, int C) {
    __shared__ float t[32][33];
    int c0 = blockIdx.x * 32, r0 = blockIdx.y * 32;
    #pragma unroll
    for (int j = 0; j < 32; j += 8)
        t[threadIdx.y + j][threadIdx.x] = in[(size_t)(r0 + threadIdx.y + j) * C + c0 + threadIdx.x];
    __syncthreads();
    #pragma unroll
    for (int j = 0; j < 32; j += 8) {
        float v = t[threadIdx.x][threadIdx.y + j];
        half h, l; split1(v, h, l);
        size_t o = (size_t)(c0 + threadIdx.y + j) * R + r0 + threadIdx.x;
        oh[o] = h;
        if (ol) ol[o] = l;
    }
}

// embed gather -> fp16 only
__global__ void k_embed_gather(const int* __restrict__ x_in, const int* __restrict__ mask,
                               const float* __restrict__ embed, half* __restrict__ X0h) {
    int r = blockIdx.x;
    int idx = x_in[r];
    float m = (mask[r] != 0) ? 1.f : 0.f;
    const float4* src = (const float4*)(embed + (size_t)idx * DV);
    for (int t = threadIdx.x; t < DV / 4; t += blockDim.x) {
        float4 v = src[t];
        v.x *= m; v.y *= m; v.z *= m; v.w *= m;
        size_t o = ((size_t)r * DV) / 2 + 2 * t;
        ((__half2*)X0h)[o]   = __halves2half2(__float2half_rn(v.x), __float2half_rn(v.y));
        ((__half2*)X0h)[o+1] = __halves2half2(__float2half_rn(v.z), __float2half_rn(v.w));
    }
}

// residual (fp16 x0) + layernorm + mask -> fp16
__global__ void k_ln(const float* __restrict__ y2, const half* __restrict__ x0h,
                     const int* __restrict__ mask,
                     const float* __restrict__ g, const float* __restrict__ b,
                     half* __restrict__ oh) {
    int r = blockIdx.x, tid = threadIdx.x;
    size_t base = (size_t)r * DV;
    float v0 = y2[base + tid]       + __half2float(x0h[base + tid]);
    float v1 = y2[base + tid + 256] + __half2float(x0h[base + tid + 256]);
    float s = v0 + v1, s2 = v0 * v0 + v1 * v1;
    __shared__ float sh1[8], sh2[8];
    __shared__ float s_mu, s_iv;
    #pragma unroll
    for (int o = 16; o > 0; o >>= 1) {
        s  += __shfl_down_sync(0xffffffffu, s,  o);
        s2 += __shfl_down_sync(0xffffffffu, s2, o);
    }
    if ((tid & 31) == 0) { sh1[tid >> 5] = s; sh2[tid >> 5] = s2; }
    __syncthreads();
    if (tid == 0) {
        float t1 = 0.f, t2 = 0.f;
        #pragma unroll
        for (int w = 0; w < 8; w++) { t1 += sh1[w]; t2 += sh2[w]; }
        float mu = t1 * (1.0f / DV);
        float var = t2 * (1.0f / DV) - mu * mu;
        s_mu = mu; s_iv = rsqrtf(var + 1e-5f);
    }
    __syncthreads();
    float mu = s_mu, iv = s_iv;
    float m = (mask[r] != 0) ? 1.f : 0.f;
    float o0 = ((v0 - mu) * iv * g[tid]       + b[tid])       * m;
    float o1 = ((v1 - mu) * iv * g[tid + 256] + b[tid + 256]) * m;
    oh[base + tid]       = __float2half_rn(o0);
    oh[base + tid + 256] = __float2half_rn(o1);
}

// ---------------- fp16 GEMM, tile 128x128, BK=64, 256 thr, 2 CTA/SM ----
// C[m,n] = sum_k A[m,k]*Bt[n,k];  A: fp16 hi only.
// BLO=1: B hi/lo 2-pass, 2-stage pipeline, 2 syncs/chunk (stage 55296 B).
// BLO=0: B hi only,      3-stage pipeline, 1 sync/chunk  (stage 36864 B).
#define SMEMSZ 110592   // = 2*55296 = 3*36864; also covers 128x132 f32 epilogue (67584)

template <int MODE, int EPI, int OUT, int BLO>
__global__ void __launch_bounds__(256, 2)
mma_gemm(const half* __restrict__ Ah,
         const half* __restrict__ Bh, const half* __restrict__ Bl,
         const float* __restrict__ aux, const float* __restrict__ invs,
         float* __restrict__ Cf, half* __restrict__ Chi, half* __restrict__ Clo,
         int Ncols, int Kd, int lda) {
    constexpr int NSTG = BLO ? 2 : 3;
    constexpr uint32_t STGSZ = BLO ? 55296u : 36864u;
    extern __shared__ __align__(128) char smem[];
    uint32_t sb = smem_u32(smem);
    const int tid = threadIdx.x;
    const int bm = blockIdx.y << 7, bn = blockIdx.x << 7;
    const int w = tid >> 5;
    const int rm = (w >> 1) << 5;   // warp row base (0,32,64,96)
    const int cn = (w & 1) << 6;    // warp col base (0,64)

    wmma::fragment<wmma::accumulator, 16, 16, 16, float> acc[2][4];
    #pragma unroll
    for (int mt = 0; mt < 2; mt++)
        #pragma unroll
        for (int nt = 0; nt < 4; nt++) wmma::fill_fragment(acc[mt][nt], 0.f);

    const int nch = Kd >> 6;

    auto issue = [&](int ch) {
        int k0 = ch << 6;
        uint32_t st = sb + (uint32_t)(ch % NSTG) * STGSZ;
        #pragma unroll
        for (int t = 0; t < 12; t++) {
            int c = tid + (t << 8);          // 0..3071
            if (!BLO && c >= 2048) break;    // no Bl region in 3-stage mode
            int row = (c & 1023) >> 3;       // 0..127
            int seg = c & 7;                 // 16B segment within 64-wide K chunk
            uint32_t doff = (uint32_t)row * 144u + (uint32_t)(seg << 4);
            if (c < 1024) {
                if (MODE == 0) {
                    size_t so = (size_t)(bm + row) * lda + k0 + (seg << 3);
                    cpa16(st + doff, Ah + so, 16);
                } else {
                    int kk = k0 >> 9;        // tap, constant per 64-chunk
                    int icol = (k0 & 511) + (seg << 3);
                    int rg = bm + row;
                    int valid = ((rg & (NS - 1)) + kk) >= 2;
                    size_t so = (size_t)(valid ? rg + kk - 2 : rg) * 512 + icol;
                    cpa16(st + doff, Ah + so, valid ? 16 : 0);
                }
            } else if (c < 2048) {
                size_t so = (size_t)(bn + row) * Kd + k0 + (seg << 3);
                cpa16(st + 18432 + doff, Bh + so, 16);
            } else {
                size_t so = (size_t)(bn + row) * Kd + k0 + (seg << 3);
                cpa16(st + 36864 + doff, Bl + so, 16);
            }
        }
        asm volatile("cp.async.commit_group;" ::: "memory");
    };

    auto compute = [&](int ch) {
        const half* pA  = (const half*)(smem + (ch % NSTG) * STGSZ);
        const half* pBh = pA + 9216;
        const half* pBl = pA + 18432;
        #pragma unroll
        for (int ks = 0; ks < 64; ks += 16) {
            wmma::fragment<wmma::matrix_a, 16, 16, 16, half, wmma::row_major> fah[2];
            #pragma unroll
            for (int mt = 0; mt < 2; mt++)
                wmma::load_matrix_sync(fah[mt], pA + (rm + mt * 16) * 72 + ks, 72);
            #pragma unroll
            for (int nt = 0; nt < 4; nt++) {
                wmma::fragment<wmma::matrix_b, 16, 16, 16, half, wmma::col_major> fbh;
                wmma::load_matrix_sync(fbh, pBh + (cn + nt * 16) * 72 + ks, 72);
                #pragma unroll
                for (int mt = 0; mt < 2; mt++)
                    wmma::mma_sync(acc[mt][nt], fah[mt], fbh, acc[mt][nt]);
                if (BLO) {
                    wmma::fragment<wmma::matrix_b, 16, 16, 16, half, wmma::col_major> fbl;
                    wmma::load_matrix_sync(fbl, pBl + (cn + nt * 16) * 72 + ks, 72);
                    #pragma unroll
                    for (int mt = 0; mt < 2; mt++)
                        wmma::mma_sync(acc[mt][nt], fah[mt], fbl, acc[mt][nt]);
                }
            }
        }
    };

    if (BLO) {
        // 2-stage, 2 syncs per chunk (proven path for hi/lo GEMMs)
        issue(0);
        for (int ch = 0; ch < nch; ch++) {
            __syncthreads();
            if (ch + 1 < nch) {
                issue(ch + 1);
                asm volatile("cp.async.wait_group 1;" ::: "memory");
            } else {
                asm volatile("cp.async.wait_group 0;" ::: "memory");
            }
            __syncthreads();
            compute(ch);
        }
    } else {
        // 3-stage ring, single sync per chunk
        issue(0);
        if (nch > 1) issue(1);
        for (int ch = 0; ch < nch; ch++) {
            if (ch + 1 < nch) {
                asm volatile("cp.async.wait_group 1;" ::: "memory");
            } else {
                asm volatile("cp.async.wait_group 0;" ::: "memory");
            }
            __syncthreads();   // chunk ch visible to all; buffer (ch+2)%3 free (compute ch-1 done)
            if (ch + 2 < nch) issue(ch + 2);
            compute(ch);
        }
    }

    if (EPI == 0 && OUT == 0) {
        // direct fragment store to gmem (logits, G)
        #pragma unroll
        for (int mt = 0; mt < 2; mt++)
            #pragma unroll
            for (int nt = 0; nt < 4; nt++)
                wmma::store_matrix_sync(
                    Cf + (size_t)(bm + rm + mt * 16) * Ncols + bn + cn + nt * 16,
                    acc[mt][nt], Ncols, wmma::mem_row_major);
        return;
    }

    // ---- epilogue via smem (128x132 fp32 = 67584 B, covered by SMEMSZ) ----
    __syncthreads();
    float* Cbuf = (float*)smem;
    #pragma unroll
    for (int mt = 0; mt < 2; mt++)
        #pragma unroll
        for (int nt = 0; nt < 4; nt++)
            wmma::store_matrix_sync(Cbuf + (rm + mt * 16) * 132 + cn + nt * 16,
                                    acc[mt][nt], 132, wmma::mem_row_major);
    __syncthreads();

    int row = tid >> 1;
    int cp = (tid & 1) << 6;
    int grow = bm + row;
    float ivv = (EPI == 3) ? invs[grow] : 0.f;
    #pragma unroll
    for (int j = 0; j < 64; j += 4) {
        int col = cp + j;
        float v0 = Cbuf[row * 132 + col + 0];
        float v1 = Cbuf[row * 132 + col + 1];
        float v2 = Cbuf[row * 132 + col + 2];
        float v3 = Cbuf[row * 132 + col + 3];
        if (EPI == 1 || EPI == 2) {
            float4 bi = *(const float4*)(aux + bn + col);
            v0 += bi.x; v1 += bi.y; v2 += bi.z; v3 += bi.w;
            if (EPI == 2) {
                v0 = fmaxf(v0, 0.f); v1 = fmaxf(v1, 0.f);
                v2 = fmaxf(v2, 0.f); v3 = fmaxf(v3, 0.f);
            }
        } else if (EPI == 3) {
            float4 xs = *(const float4*)(aux + (size_t)grow * 512 + bn + col);
            v0 = ivv * (v0 + xs.x); v1 = ivv * (v1 + xs.y);
            v2 = ivv * (v2 + xs.z); v3 = ivv * (v3 + xs.w);
        }
        size_t off = (size_t)grow * Ncols + bn + col;
        if (OUT == 0) {
            *(float4*)(Cf + off) = make_float4(v0, v1, v2, v3);
        } else {
            __half2* ph = (__half2*)(Chi + off);
            ph[0] = __halves2half2(__float2half_rn(v0), __float2half_rn(v1));
            ph[1] = __halves2half2(__float2half_rn(v2), __float2half_rn(v3));
        }
    }
}

// ---------------- launch ----------------
extern "C" void kernel_launch(void* const* d_in, const int* in_sizes, int n_in,
                              void* d_out, int out_size) {
    const int*   x_in  = (const int*)d_in[0];
    const int*   mask  = (const int*)d_in[1];
    const int*   subn  = (const int*)d_in[2];
    const float* A_sub = (const float*)d_in[3];
    const float* embed = (const float*)d_in[4];
    const float* c1w   = (const float*)d_in[5];
    const float* c1b   = (const float*)d_in[6];
    const float* c2w   = (const float*)d_in[7];
    const float* c2b   = (const float*)d_in[8];
    const float* lng   = (const float*)d_in[9];
    const float* lnb   = (const float*)d_in[10];
    const float* gcnw  = (const float*)d_in[11];
    const float* gcnb  = (const float*)d_in[12];
    const float* hpw   = (const float*)d_in[13];
    float*       out   = (float*)d_out;

    float *Y2, *Xs, *inv;
    half *Ash, *XsTh, *XsTl, *AXh, *Hch, *Gh, *gwh, *gwl, *hph, *hpl;
    half *w1Th, *w2Th, *X0h, *Y1h, *Y2h;
    cudaGetSymbolAddress((void**)&Y2,  g_Y2);
    cudaGetSymbolAddress((void**)&Xs,  g_Xs);
    cudaGetSymbolAddress((void**)&inv, g_inv);
    cudaGetSymbolAddress((void**)&Ash, g_Ash);
    cudaGetSymbolAddress((void**)&XsTh, g_XsTh); cudaGetSymbolAddress((void**)&XsTl, g_XsTl);
    cudaGetSymbolAddress((void**)&AXh, g_AXh);
    cudaGetSymbolAddress((void**)&Hch, g_Hch);
    cudaGetSymbolAddress((void**)&Gh,  g_Gh);
    cudaGetSymbolAddress((void**)&gwh, g_gwh);   cudaGetSymbolAddress((void**)&gwl, g_gwl);
    cudaGetSymbolAddress((void**)&hph, g_hph);   cudaGetSymbolAddress((void**)&hpl, g_hpl);
    cudaGetSymbolAddress((void**)&w1Th, g_w1Th);
    cudaGetSymbolAddress((void**)&w2Th, g_w2Th);
    cudaGetSymbolAddress((void**)&X0h, g_X0h);
    cudaGetSymbolAddress((void**)&Y1h, g_Y1h);
    cudaGetSymbolAddress((void**)&Y2h, g_Y2h);

    cudaFuncSetAttribute(mma_gemm<0,3,1,1>, cudaFuncAttributeMaxDynamicSharedMemorySize, SMEMSZ);
    cudaFuncSetAttribute(mma_gemm<0,2,1,1>, cudaFuncAttributeMaxDynamicSharedMemorySize, SMEMSZ);
    cudaFuncSetAttribute(mma_gemm<1,2,1,0>, cudaFuncAttributeMaxDynamicSharedMemorySize, SMEMSZ);
    cudaFuncSetAttribute(mma_gemm<1,1,0,0>, cudaFuncAttributeMaxDynamicSharedMemorySize, SMEMSZ);
    cudaFuncSetAttribute(mma_gemm<0,0,0,1>, cudaFuncAttributeMaxDynamicSharedMemorySize, SMEMSZ);
    cudaFuncSetAttribute(mma_gemm<0,0,0,0>, cudaFuncAttributeMaxDynamicSharedMemorySize, SMEMSZ);

    // fork/join resources, created once (outside capture on the first call)
    static cudaStream_t s_gcn = nullptr;
    static cudaEvent_t ev_fork = nullptr, ev_join = nullptr;
    if (!s_gcn) {
        cudaStreamCreateWithFlags(&s_gcn, cudaStreamNonBlocking);
        cudaEventCreateWithFlags(&ev_fork, cudaEventDisableTiming);
        cudaEventCreateWithFlags(&ev_join, cudaEventDisableTiming);
    }
    cudaStream_t sm = cudaStreamPerThread;

    dim3 t32(32, 8);

    // ---- fork ----
    cudaEventRecord(ev_fork, sm);
    cudaStreamWaitEvent(s_gcn, ev_fork, 0);

    // ---- GCN branch (side stream) ----
    k_deg<<<NN, 256, 0, s_gcn>>>(A_sub, inv);
    k_gather_xs<<<NN, 128, 0, s_gcn>>>(subn, embed, inv, Xs);
    k_transpose_split<<<dim3(DV/32, NN/32), t32, 0, s_gcn>>>(Xs, XsTh, XsTl, NN, DV);
    k_cvt_hi<<<NN*NN/4/256, 256, 0, s_gcn>>>((const float4*)A_sub, Ash, NN*NN/4);
    mma_gemm<0,3,1,1><<<dim3(DV/128, NN/128), 256, SMEMSZ, s_gcn>>>(
        Ash, XsTh, XsTl, Xs, inv, nullptr, AXh, nullptr, DV, NN, NN);
    k_split<<<DV*DV/4/256, 256, 0, s_gcn>>>((const float4*)gcnw, gwh, gwl, DV*DV/4);
    mma_gemm<0,2,1,1><<<dim3(DV/128, NN/128), 256, SMEMSZ, s_gcn>>>(
        AXh, gwh, gwl, gcnb, nullptr, nullptr, Hch, nullptr, DV, DV, DV);
    k_transpose_split<<<dim3(DV/32, DV/32), t32, 0, s_gcn>>>(hpw, hph, hpl, DV, DV);
    mma_gemm<0,0,0,1><<<dim3(DV/128, NN/128), 256, SMEMSZ, s_gcn>>>(
        Hch, hph, hpl, nullptr, nullptr, Xs, nullptr, nullptr, DV, DV, DV);
    k_cvt_hi<<<NN*DV/4/256, 256, 0, s_gcn>>>((const float4*)Xs, Gh, NN*DV/4);
    cudaEventRecord(ev_join, s_gcn);

    // ---- encoder branch (main stream) ----
    k_embed_gather<<<NBS, 128, 0, sm>>>(x_in, mask, embed, X0h);
    k_transpose_split<<<dim3(DV/32, KCONV/32), t32, 0, sm>>>(c1w, w1Th, nullptr, KCONV, DV);
    k_transpose_split<<<dim3(DV/32, KCONV/32), t32, 0, sm>>>(c2w, w2Th, nullptr, KCONV, DV);
    mma_gemm<1,2,1,0><<<dim3(DV/128, NBS/128), 256, SMEMSZ, sm>>>(
        X0h, w1Th, nullptr, c1b, nullptr, nullptr, Y1h, nullptr, DV, KCONV, 512);
    mma_gemm<1,1,0,0><<<dim3(DV/128, NBS/128), 256, SMEMSZ, sm>>>(
        Y1h, w2Th, nullptr, c2b, nullptr, Y2, nullptr, nullptr, DV, KCONV, 512);
    k_ln<<<NBS, 256, 0, sm>>>(Y2, X0h, mask, lng, lnb, Y2h);

    // ---- join, then logits = y @ G^T (1-pass, direct fragment store) ----
    cudaStreamWaitEvent(sm, ev_join, 0);
    mma_gemm<0,0,0,0><<<dim3(NN/128, NBS/128), 256, SMEMSZ, sm>>>(
        Y2h, Gh, nullptr, nullptr, nullptr, out, nullptr, nullptr, NN, DV, DV);
}